// round 14
// baseline (speedup 1.0000x reference)
#include <cuda_runtime.h>

#define BATCH 2048
#define TT    512
#define HID   64
#define NB    7       // rows per CTA (296 CTAs = exactly 2 per SM)
#define NCTA  296
#define NTHR  256

typedef unsigned long long u64;

__device__ __forceinline__ u64 ffma2(u64 a, u64 b, u64 c) {
    u64 d;
    asm("fma.rn.f32x2 %0, %1, %2, %3;" : "=l"(d) : "l"(a), "l"(b), "l"(c));
    return d;
}

__device__ __forceinline__ float sum2(u64 v) {
    float lo, hi;
    asm("mov.b64 {%0, %1}, %2;" : "=f"(lo), "=f"(hi) : "l"(v));
    return lo + hi;
}

__device__ __forceinline__ float tanh_fast(float v) {
    float r;
    asm("tanh.approx.f32 %0, %1;" : "=f"(r) : "f"(v));
    return r;
}

__global__ __launch_bounds__(NTHR, 2)
void lstm_kernel(const float* __restrict__ x,
                 const float* __restrict__ W_ih,
                 const float* __restrict__ W_hh,
                 const float* __restrict__ b_ih,
                 const float* __restrict__ b_hh,
                 const float* __restrict__ W_d,
                 const float* __restrict__ b_d,
                 float* __restrict__ out) {
    __shared__ float x_s[NB][TT];        // 14 KB
    __shared__ float h_s[2][NB][HID];    // 3.5 KB, ping-pong on t parity

    const int tid   = threadIdx.x;
    const int lane  = tid & 31;
    const int warp  = tid >> 5;                 // 0..7
    const int kh    = lane >> 4;                // k-half: 0 -> k[0,32), 1 -> k[32,64)
    const int j     = lane & 7;                 // unit-within-warp 0..7
    const int half8 = (lane >> 3) & 1;          // 0: i/g column, 1: f/o column
    // gate-aligned mapping: warp w owns all 4 gates of units 8w..8w+7
    const int cp    = (warp << 3) + j + (half8 << 6);   // column-pair id
    const int colA  = cp;                       // i (half8=0) or f (half8=1)
    const int colB  = cp + 128;                 // g (half8=0) or o (half8=1)
    const int mycol = kh ? colB : colA;         // column this thread finalizes
    const bool isTanh = (kh == 1) && (half8 == 0);      // g gate
    // branchless activation: act(v) = s0 + s1*tanh(sc*v)
    const float s0 = isTanh ? 0.0f : 0.5f;
    const float s1 = isTanh ? 1.0f : 0.5f;
    const float sc = isTanh ? 1.0f : 0.5f;
    const bool upd = (lane < 8);                // lanes holding the i gate do phase 2
    const int mu   = (warp << 3) + j;           // hidden unit updated by this lane

    const int row0 = blockIdx.x * NB;

    // --- weights: k-half of both owned columns (64 regs total, R8 layout) ---
    u64 wA[16], wB[16];
    {
        const ulonglong2* pa = reinterpret_cast<const ulonglong2*>(W_hh + colA * HID + kh * 32);
        const ulonglong2* pb = reinterpret_cast<const ulonglong2*>(W_hh + colB * HID + kh * 32);
#pragma unroll
        for (int q = 0; q < 8; q++) {
            ulonglong2 va = pa[q];
            wA[2 * q + 0] = va.x;  wA[2 * q + 1] = va.y;
            ulonglong2 vb = pb[q];
            wB[2 * q + 0] = vb.x;  wB[2 * q + 1] = vb.y;
        }
    }
    const float bias = b_ih[mycol] + b_hh[mycol];
    const float wih  = W_ih[mycol];
    const int khoff  = kh * 32;

    // --- stage x slab (coalesced; clamp rows past BATCH) ---
    for (int i = tid; i < NB * TT; i += NTHR) {
        int r = i / TT;
        int t = i % TT;
        int gr = row0 + r;
        if (gr > BATCH - 1) gr = BATCH - 1;
        x_s[r][t] = x[gr * TT + t];
    }
    for (int i = tid; i < NB * HID; i += NTHR)
        ((float*)h_s[0])[i] = 0.0f;

    // c state: update lanes own c for (row, unit mu)
    float c[NB];
#pragma unroll
    for (int r = 0; r < NB; r++) c[r] = 0.0f;

    __syncthreads();

    for (int t = 0; t < TT; t++) {
        const float* hr = &h_s[t & 1][0][0];          // read buffer
        float*       hw = &h_s[(t + 1) & 1][0][0];    // write buffer

        // hoisted x loads (broadcast, MLP batch)
        float xv[NB];
#pragma unroll
        for (int r = 0; r < NB; r++) xv[r] = x_s[r][t];

        // ---------- phase 1+2 fused, software-pipelined over rows (R8 shape) ----------
        ulonglong2 hva[4], hvb[4];
#pragma unroll
        for (int q = 0; q < 4; q++)        // prologue: row 0, half 0
            hva[q] = *reinterpret_cast<const ulonglong2*>(hr + khoff + q * 4);

#pragma unroll
        for (int r = 0; r < NB; r++) {
            // load half 1 of row r
#pragma unroll
            for (int q = 0; q < 4; q++)
                hvb[q] = *reinterpret_cast<const ulonglong2*>(hr + r * HID + khoff + 16 + q * 4);

            u64 aA = 0ull, aB = 0ull;
            // consume half 0
#pragma unroll
            for (int q = 0; q < 4; q++) {
                aA = ffma2(wA[2 * q + 0], hva[q].x, aA);
                aA = ffma2(wA[2 * q + 1], hva[q].y, aA);
                aB = ffma2(wB[2 * q + 0], hva[q].x, aB);
                aB = ffma2(wB[2 * q + 1], hva[q].y, aB);
            }
            // prefetch half 0 of row r+1 (overlaps half-1 FMAs below)
            if (r + 1 < NB) {
#pragma unroll
                for (int q = 0; q < 4; q++)
                    hva[q] = *reinterpret_cast<const ulonglong2*>(hr + (r + 1) * HID + khoff + q * 4);
            }
            // consume half 1
#pragma unroll
            for (int q = 0; q < 4; q++) {
                aA = ffma2(wA[8 + 2 * q + 0], hvb[q].x, aA);
                aA = ffma2(wA[8 + 2 * q + 1], hvb[q].y, aA);
                aB = ffma2(wB[8 + 2 * q + 0], hvb[q].x, aB);
                aB = ffma2(wB[8 + 2 * q + 1], hvb[q].y, aB);
            }

            // reduce across k-half partner (lane ^ 16), convergent (R8 verbatim)
            float pA = sum2(aA), pB = sum2(aB);
            float send = kh ? pA : pB;
            float recv = __shfl_xor_sync(0xffffffffu, send, 16);
            float own  = kh ? pB : pA;
            float tot  = fmaf(xv[r], wih, bias) + own + recv;
            float act  = fmaf(s1, tanh_fast(sc * tot), s0);

            // warp-local gate gather: unit mu's gates sit at lanes j, j+8, j+16, j+24
            float r_f = __shfl_xor_sync(0xffffffffu, act, 8);
            float r_g = __shfl_xor_sync(0xffffffffu, act, 16);
            float r_o = __shfl_xor_sync(0xffffffffu, act, 24);

            if (upd) {    // act == i gate on these lanes
                c[r] = fmaf(r_f, c[r], act * r_g);
                hw[r * HID + mu] = r_o * tanh_fast(c[r]);
            }
        }
        __syncthreads();   // single barrier per step (h double-buffered, g_s gone)
    }

    // ---------- final projection: h_T lives in buffer (TT & 1) == 0 ----------
    if (tid < NB && row0 + tid < BATCH) {
        float s = b_d[0];
#pragma unroll
        for (int mm = 0; mm < HID; mm++)
            s = fmaf(h_s[0][tid][mm], W_d[mm], s);
        out[row0 + tid] = s;
    }
}

extern "C" void kernel_launch(void* const* d_in, const int* in_sizes, int n_in,
                              void* d_out, int out_size) {
    const float* x    = (const float*)d_in[0];
    const float* W_ih = (const float*)d_in[1];
    const float* W_hh = (const float*)d_in[2];
    const float* b_ih = (const float*)d_in[3];
    const float* b_hh = (const float*)d_in[4];
    const float* W_d  = (const float*)d_in[5];
    const float* b_d  = (const float*)d_in[6];
    float* out = (float*)d_out;

    lstm_kernel<<<NCTA, NTHR>>>(x, W_ih, W_hh, b_ih, b_hh, W_d, b_d, out);
}

// round 15
// speedup vs baseline: 1.1252x; 1.1252x over previous
#include <cuda_runtime.h>

#define BATCH 2048
#define TT    512
#define HID   64
#define NB    7       // rows per CTA (296 CTAs = exactly 2 per SM)
#define NCTA  296
#define NTHR  256
// g_s layout: i at [0,64), f at [64,128), PAD 16, g at [144,208), o at [208,272)
// pad shifts colB stores by 16 banks -> STS half-warps hit disjoint banks (1 wf)
#define GOFF  144
#define GROW  272

typedef unsigned long long u64;

__device__ __forceinline__ u64 ffma2(u64 a, u64 b, u64 c) {
    u64 d;
    asm("fma.rn.f32x2 %0, %1, %2, %3;" : "=l"(d) : "l"(a), "l"(b), "l"(c));
    return d;
}

__device__ __forceinline__ float sum2(u64 v) {
    float lo, hi;
    asm("mov.b64 {%0, %1}, %2;" : "=f"(lo), "=f"(hi) : "l"(v));
    return lo + hi;
}

__device__ __forceinline__ float tanh_fast(float v) {
    float r;
    asm("tanh.approx.f32 %0, %1;" : "=f"(r) : "f"(v));
    return r;
}

__global__ __launch_bounds__(NTHR, 2)
void lstm_kernel(const float* __restrict__ x,
                 const float* __restrict__ W_ih,
                 const float* __restrict__ W_hh,
                 const float* __restrict__ b_ih,
                 const float* __restrict__ b_hh,
                 const float* __restrict__ W_d,
                 const float* __restrict__ b_d,
                 float* __restrict__ out) {
    __shared__ float x_s[NB][TT];      // 14 KB
    __shared__ float h_s[NB][HID];     // 1.75 KB
    __shared__ float g_s[NB][GROW];    // 7.4 KB (padded gate blocks)

    const int tid  = threadIdx.x;
    const int lane = tid & 31;
    const int warp = tid >> 5;                    // 0..7
    const int kh   = lane >> 4;                   // k-half: 0 -> k[0,32), 1 -> k[32,64)
    const int cp   = (warp << 4) | (lane & 15);   // column-pair id 0..127
    const int colA = cp;                          // i/f column (always sigmoid)
    const int colB = cp + 128;                    // g/o column
    const int mycol = kh ? colB : colA;           // column this thread finalizes
    const bool isTanh = (kh == 1) && (warp < 4);  // colB in g-range [128,192)
    // branchless activation: act(v) = s0 + s1*tanh(sc*v)
    const float s0 = isTanh ? 0.0f : 0.5f;
    const float s1 = isTanh ? 1.0f : 0.5f;
    const float sc = isTanh ? 1.0f : 0.5f;
    // padded store address: colA -> [0,128), colB -> [144,272)
    const int gaddr = kh ? (GOFF + (mycol - 128)) : mycol;

    const int row0 = blockIdx.x * NB;

    // --- weights: k-half of both owned columns (64 regs total, proven R8) ---
    u64 wA[16], wB[16];
    {
        const ulonglong2* pa = reinterpret_cast<const ulonglong2*>(W_hh + colA * HID + kh * 32);
        const ulonglong2* pb = reinterpret_cast<const ulonglong2*>(W_hh + colB * HID + kh * 32);
#pragma unroll
        for (int q = 0; q < 8; q++) {
            ulonglong2 va = pa[q];
            wA[2 * q + 0] = va.x;  wA[2 * q + 1] = va.y;
            ulonglong2 vb = pb[q];
            wB[2 * q + 0] = vb.x;  wB[2 * q + 1] = vb.y;
        }
    }
    const float bias = b_ih[mycol] + b_hh[mycol];
    const float wih  = W_ih[mycol];
    const int khoff  = kh * 32;

    // --- stage x slab (coalesced; clamp rows past BATCH) ---
    for (int i = tid; i < NB * TT; i += NTHR) {
        int r = i / TT;
        int t = i % TT;
        int gr = row0 + r;
        if (gr > BATCH - 1) gr = BATCH - 1;
        x_s[r][t] = x[gr * TT + t];
    }
    for (int i = tid; i < NB * HID; i += NTHR)
        ((float*)h_s)[i] = 0.0f;

    // --- phase-2 ownership: NB*HID = 448 cell states ---
    float c0 = 0.0f, c1 = 0.0f;
    const int r0a = tid >> 6,            m0 = tid & 63;
    const bool has1 = (tid < NB * HID - NTHR);   // tid < 192
    const int idx1 = tid + NTHR;
    const int r1a = idx1 >> 6,           m1 = idx1 & 63;

    __syncthreads();

    for (int t = 0; t < TT; t++) {
        // hoisted x loads for all rows (broadcast, MLP batch)
        float xv[NB];
#pragma unroll
        for (int r = 0; r < NB; r++) xv[r] = x_s[r][t];

        // ---------- phase 1: software-pipelined over rows (R8 verbatim) ----------
        ulonglong2 hva[4], hvb[4];
#pragma unroll
        for (int q = 0; q < 4; q++)        // prologue: row 0, half 0
            hva[q] = *reinterpret_cast<const ulonglong2*>(&h_s[0][khoff + q * 4]);

#pragma unroll
        for (int r = 0; r < NB; r++) {
            // load half 1 of row r
#pragma unroll
            for (int q = 0; q < 4; q++)
                hvb[q] = *reinterpret_cast<const ulonglong2*>(&h_s[r][khoff + 16 + q * 4]);

            u64 aA = 0ull, aB = 0ull;
            // consume half 0
#pragma unroll
            for (int q = 0; q < 4; q++) {
                aA = ffma2(wA[2 * q + 0], hva[q].x, aA);
                aA = ffma2(wA[2 * q + 1], hva[q].y, aA);
                aB = ffma2(wB[2 * q + 0], hva[q].x, aB);
                aB = ffma2(wB[2 * q + 1], hva[q].y, aB);
            }
            // prefetch half 0 of row r+1 (overlaps half-1 FMAs below)
            if (r + 1 < NB) {
#pragma unroll
                for (int q = 0; q < 4; q++)
                    hva[q] = *reinterpret_cast<const ulonglong2*>(&h_s[r + 1][khoff + q * 4]);
            }
            // consume half 1
#pragma unroll
            for (int q = 0; q < 4; q++) {
                aA = ffma2(wA[8 + 2 * q + 0], hvb[q].x, aA);
                aA = ffma2(wA[8 + 2 * q + 1], hvb[q].y, aA);
                aB = ffma2(wB[8 + 2 * q + 0], hvb[q].x, aB);
                aB = ffma2(wB[8 + 2 * q + 1], hvb[q].y, aB);
            }

            // reduce across k-half partner (lane ^ 16), convergent
            float pA = sum2(aA), pB = sum2(aB);
            float send = kh ? pA : pB;
            float recv = __shfl_xor_sync(0xffffffffu, send, 16);
            float own  = kh ? pB : pA;
            float tot  = fmaf(xv[r], wih, bias) + own + recv;
            g_s[r][gaddr] = fmaf(s1, tanh_fast(sc * tot), s0);   // 1-wavefront STS
        }
        __syncthreads();

        // ---------- phase 2: batch all 8 gate loads first (MLP=8), then compute ----
        {
            float i0 = g_s[r0a][m0];
            float f0 = g_s[r0a][64 + m0];
            float g0 = g_s[r0a][GOFF + m0];
            float o0 = g_s[r0a][GOFF + 64 + m0];
            float i1 = 0.f, f1 = 0.f, g1 = 0.f, o1 = 0.f;
            if (has1) {
                i1 = g_s[r1a][m1];
                f1 = g_s[r1a][64 + m1];
                g1 = g_s[r1a][GOFF + m1];
                o1 = g_s[r1a][GOFF + 64 + m1];
            }
            c0 = fmaf(f0, c0, i0 * g0);
            h_s[r0a][m0] = o0 * tanh_fast(c0);
            if (has1) {
                c1 = fmaf(f1, c1, i1 * g1);
                h_s[r1a][m1] = o1 * tanh_fast(c1);
            }
        }
        __syncthreads();
    }

    // ---------- final projection ----------
    if (tid < NB && row0 + tid < BATCH) {
        float s = b_d[0];
#pragma unroll
        for (int m = 0; m < HID; m++)
            s = fmaf(h_s[tid][m], W_d[m], s);
        out[row0 + tid] = s;
    }
}

extern "C" void kernel_launch(void* const* d_in, const int* in_sizes, int n_in,
                              void* d_out, int out_size) {
    const float* x    = (const float*)d_in[0];
    const float* W_ih = (const float*)d_in[1];
    const float* W_hh = (const float*)d_in[2];
    const float* b_ih = (const float*)d_in[3];
    const float* b_hh = (const float*)d_in[4];
    const float* W_d  = (const float*)d_in[5];
    const float* b_d  = (const float*)d_in[6];
    float* out = (float*)d_out;

    lstm_kernel<<<NCTA, NTHR>>>(x, W_ih, W_hh, b_ih, b_hh, W_d, b_d, out);
}